// round 2
// baseline (speedup 1.0000x reference)
#include <cuda_runtime.h>
#include <math.h>

typedef unsigned long long u64;

#define NROWS 1048576ull

// ---------- packed f32x2 helpers (sm_103a) ----------
__device__ __forceinline__ u64 ffma2(u64 acc, u64 a, u64 b) {
    u64 d;
    asm("fma.rn.f32x2 %0, %1, %2, %3;" : "=l"(d) : "l"(a), "l"(b), "l"(acc));
    return d;
}
__device__ __forceinline__ float2 u2f(u64 v) {
    float2 f;
    asm("mov.b64 {%0, %1}, %2;" : "=f"(f.x), "=f"(f.y) : "l"(v));
    return f;
}

// ---------- scratch (device globals; no runtime alloc) ----------
__device__ float g_m1[NROWS * 64];      // m1, reused as z1
__device__ float g_m2[NROWS * 64];      // m2, reused as z2
__device__ float g_h [NROWS * 64];      // sqrt(relu(corr))
__device__ float g_part[8192 * 128];    // per-CTA [sum(64)|sumsq(64)]
__device__ float g_red [256 * 128];
__device__ float g_ss1[128];            // BN1 [scale(64)|shift(64)]
__device__ float g_ss2[128];            // BN2

// ---------- generic register-tiled GEMM core ----------
// in_s: rows with stride RS floats. W_s: float2-packed, Wt[k2*64+o] = (W_k(2k2,o), W_k(2k2+1,o)).
// thread computes rows r0..r0+7, outs og*4..og*4+3. z = in @ W (no bias).
template<int KP, int RS>
__device__ __forceinline__ void gemm_tile(const float* __restrict__ in_s,
                                          const float* __restrict__ W_s,
                                          int og, int r0, float z[8][4])
{
    const u64* Wp = (const u64*)W_s;
    u64 acc[8][4];
#pragma unroll
    for (int rr = 0; rr < 8; rr++)
#pragma unroll
        for (int oo = 0; oo < 4; oo++) acc[rr][oo] = 0ull;

#pragma unroll 4
    for (int k2 = 0; k2 < KP; k2++) {
        u64 w[4];
#pragma unroll
        for (int oo = 0; oo < 4; oo++) w[oo] = Wp[k2 * 64 + og * 4 + oo];
#pragma unroll
        for (int rr = 0; rr < 8; rr++) {
            u64 xv = *(const u64*)(in_s + (r0 + rr) * RS + 2 * k2);
#pragma unroll
            for (int oo = 0; oo < 4; oo++) acc[rr][oo] = ffma2(acc[rr][oo], xv, w[oo]);
        }
    }
#pragma unroll
    for (int rr = 0; rr < 8; rr++)
#pragma unroll
        for (int oo = 0; oo < 4; oo++) {
            float2 p = u2f(acc[rr][oo]);
            z[rr][oo] = p.x + p.y;
        }
}

// Stage out-major weight W[o][c] (64x64) -> pair-major Wt[c2*64+o]
__device__ __forceinline__ void stage_w_omajor(const float* __restrict__ w, float* W_s, int t, int nthr) {
    for (int i = t; i < 2048; i += nthr) {
        int o = i >> 5, c2 = i & 31;
        float2 v = *(const float2*)(w + o * 64 + 2 * c2);
        ((float2*)W_s)[c2 * 64 + o] = v;
    }
}
// Stage k-major weight W[k][o] (K x 64) -> Wt[k2*64+o]
__device__ __forceinline__ void stage_w_kmajor(const float* __restrict__ w, float* W_s, int KP, int t, int nthr) {
    for (int i = t; i < KP * 64; i += nthr) {
        int k2 = i >> 6, o = i & 63;
        float2 v;
        v.x = w[(2 * k2) * 64 + o];
        v.y = w[(2 * k2 + 1) * 64 + o];
        ((float2*)W_s)[k2 * 64 + o] = v;
    }
}

// ================= K1: the two 2-layer 1x1-conv MLPs =================
// 128 rows/CTA, 256 threads. smem: xs 8192 | hs 8192 | W0 4096 | W1 4096 floats.
__global__ void __launch_bounds__(256, 1) mlp_kernel(const float* __restrict__ x,
    const float* __restrict__ w11, const float* __restrict__ b11,
    const float* __restrict__ w12, const float* __restrict__ b12,
    const float* __restrict__ w21, const float* __restrict__ b21,
    const float* __restrict__ w22, const float* __restrict__ b22)
{
    extern __shared__ float sm[];
    float* xs = sm;
    float* hs = sm + 8192;
    float* W0 = sm + 16384;
    float* W1 = sm + 20480;
    const int t = threadIdx.x;
    const int og = t & 15;
    const int r0 = (t >> 4) * 8;
    const size_t base = (size_t)blockIdx.x * 8192;

    for (int i = t; i < 8192; i += 256) xs[i] = x[base + i];
    stage_w_omajor(w11, W0, t, 256);
    stage_w_omajor(w12, W1, t, 256);
    __syncthreads();

    float z[8][4];
    float bb[4];

    // MLP1 layer 1: xs -> hs
    gemm_tile<32, 64>(xs, W0, og, r0, z);
#pragma unroll
    for (int oo = 0; oo < 4; oo++) bb[oo] = __ldg(b11 + og * 4 + oo);
#pragma unroll
    for (int rr = 0; rr < 8; rr++) {
        float4 q = make_float4(fmaxf(z[rr][0] + bb[0], 0.f), fmaxf(z[rr][1] + bb[1], 0.f),
                               fmaxf(z[rr][2] + bb[2], 0.f), fmaxf(z[rr][3] + bb[3], 0.f));
        *(float4*)(hs + (r0 + rr) * 64 + og * 4) = q;
    }
    __syncthreads();
    // MLP1 layer 2: hs -> g_m1
    gemm_tile<32, 64>(hs, W1, og, r0, z);
#pragma unroll
    for (int oo = 0; oo < 4; oo++) bb[oo] = __ldg(b12 + og * 4 + oo);
#pragma unroll
    for (int rr = 0; rr < 8; rr++) {
        float4 q = make_float4(fmaxf(z[rr][0] + bb[0], 0.f), fmaxf(z[rr][1] + bb[1], 0.f),
                               fmaxf(z[rr][2] + bb[2], 0.f), fmaxf(z[rr][3] + bb[3], 0.f));
        *(float4*)(g_m1 + base + (size_t)(r0 + rr) * 64 + og * 4) = q;
    }
    __syncthreads();

    stage_w_omajor(w21, W0, t, 256);
    stage_w_omajor(w22, W1, t, 256);
    __syncthreads();

    // MLP2 layer 1: xs -> hs
    gemm_tile<32, 64>(xs, W0, og, r0, z);
#pragma unroll
    for (int oo = 0; oo < 4; oo++) bb[oo] = __ldg(b21 + og * 4 + oo);
#pragma unroll
    for (int rr = 0; rr < 8; rr++) {
        float4 q = make_float4(fmaxf(z[rr][0] + bb[0], 0.f), fmaxf(z[rr][1] + bb[1], 0.f),
                               fmaxf(z[rr][2] + bb[2], 0.f), fmaxf(z[rr][3] + bb[3], 0.f));
        *(float4*)(hs + (r0 + rr) * 64 + og * 4) = q;
    }
    __syncthreads();
    // MLP2 layer 2: hs -> g_m2
    gemm_tile<32, 64>(hs, W1, og, r0, z);
#pragma unroll
    for (int oo = 0; oo < 4; oo++) bb[oo] = __ldg(b22 + og * 4 + oo);
#pragma unroll
    for (int rr = 0; rr < 8; rr++) {
        float4 q = make_float4(fmaxf(z[rr][0] + bb[0], 0.f), fmaxf(z[rr][1] + bb[1], 0.f),
                               fmaxf(z[rr][2] + bb[2], 0.f), fmaxf(z[rr][3] + bb[3], 0.f));
        *(float4*)(g_m2 + base + (size_t)(r0 + rr) * 64 + og * 4) = q;
    }
}

// ================= K2: corr + sqrt(relu) =================
// corr[b,i,j,c] = sum_k m1[b,i,k,c]*m2[b,k,j,c]. CTA=(b, 8-row i-tile), 512 thr.
// thread: channel-pair cp=t&31, j-group jg=t>>5 (4 j's), all 8 i's.
__global__ void __launch_bounds__(512, 1) corr_kernel()
{
    extern __shared__ float sm[];
    float* m1s = sm;          // [8i][4k][64c]  = 2048
    float* m2s = sm + 2048;   // [4k][64j][64c] = 16384
    const int t  = threadIdx.x;
    const int b  = blockIdx.x >> 3;
    const int i0 = (blockIdx.x & 7) * 8;
    const int cp = t & 31;
    const int jg = t >> 5;
    const float* M1 = g_m1 + (size_t)b * 262144 + (size_t)i0 * 4096;
    const float* M2 = g_m2 + (size_t)b * 262144;

    u64 acc[8][4];
#pragma unroll
    for (int ii = 0; ii < 8; ii++)
#pragma unroll
        for (int jj = 0; jj < 4; jj++) acc[ii][jj] = 0ull;

    for (int k0 = 0; k0 < 64; k0 += 4) {
        if (k0) __syncthreads();
        for (int i = t; i < 2048; i += 512) {
            int ii = i >> 8, kk = (i >> 6) & 3, c = i & 63;
            m1s[i] = M1[(size_t)ii * 4096 + (size_t)(k0 + kk) * 64 + c];
        }
        for (int i = t; i < 16384; i += 512) {
            int kk = i >> 12, rest = i & 4095;
            m2s[i] = M2[(size_t)(k0 + kk) * 4096 + rest];
        }
        __syncthreads();
#pragma unroll
        for (int kk = 0; kk < 4; kk++) {
            u64 a1[8];
#pragma unroll
            for (int ii = 0; ii < 8; ii++)
                a1[ii] = *(const u64*)(m1s + ii * 256 + kk * 64 + 2 * cp);
#pragma unroll
            for (int jj = 0; jj < 4; jj++) {
                u64 v = *(const u64*)(m2s + kk * 4096 + (jg * 4 + jj) * 64 + 2 * cp);
#pragma unroll
                for (int ii = 0; ii < 8; ii++) acc[ii][jj] = ffma2(acc[ii][jj], a1[ii], v);
            }
        }
    }
    float* H = g_h + (size_t)b * 262144 + (size_t)i0 * 4096;
#pragma unroll
    for (int ii = 0; ii < 8; ii++)
#pragma unroll
        for (int jj = 0; jj < 4; jj++) {
            float2 p = u2f(acc[ii][jj]);
            float2 o;
            o.x = sqrtf(fmaxf(p.x, 0.f));
            o.y = sqrtf(fmaxf(p.y, 0.f));
            *(float2*)(H + (size_t)(ii * 64 + jg * 4 + jj) * 64 + 2 * cp) = o;
        }
}

// ---------- per-CTA partial stats helper (64 channels) ----------
__device__ __forceinline__ void emit_partials(float z[8][4], float* redS, float* redQ,
                                              int og, int t, int bid)
{
    const int rgrp = t >> 4;
#pragma unroll
    for (int oo = 0; oo < 4; oo++) {
        float s = 0.f, q = 0.f;
#pragma unroll
        for (int rr = 0; rr < 8; rr++) { s += z[rr][oo]; q += z[rr][oo] * z[rr][oo]; }
        redS[rgrp * 64 + og * 4 + oo] = s;
        redQ[rgrp * 64 + og * 4 + oo] = q;
    }
    __syncthreads();
    if (t < 64) {
        float s = 0.f, q = 0.f;
#pragma unroll
        for (int g = 0; g < 16; g++) { s += redS[g * 64 + t]; q += redQ[g * 64 + t]; }
        g_part[(size_t)bid * 128 + t]      = s;
        g_part[(size_t)bid * 128 + 64 + t] = q;
    }
}

// ================= K3: z1 = [x,h] @ uW1 + ub1, + partial stats =================
// smem: cat 16384 | Wt 8192 | redS 1024 | redQ 1024 floats.
__global__ void __launch_bounds__(256, 1) gemm1_kernel(const float* __restrict__ x,
    const float* __restrict__ uW1, const float* __restrict__ ub1)
{
    extern __shared__ float sm[];
    float* cat  = sm;
    float* Wt   = sm + 16384;
    float* redS = sm + 24576;
    float* redQ = sm + 25600;
    const int t = threadIdx.x;
    const int og = t & 15;
    const int r0 = (t >> 4) * 8;
    const size_t base = (size_t)blockIdx.x * 8192;

    for (int i = t; i < 8192; i += 256) {
        int r = i >> 6, c = i & 63;
        cat[r * 128 + c]      = x[base + i];
        cat[r * 128 + 64 + c] = g_h[base + i];
    }
    stage_w_kmajor(uW1, Wt, 64, t, 256);
    __syncthreads();

    float z[8][4];
    gemm_tile<64, 128>(cat, Wt, og, r0, z);
    float bb[4];
#pragma unroll
    for (int oo = 0; oo < 4; oo++) bb[oo] = __ldg(ub1 + og * 4 + oo);
#pragma unroll
    for (int rr = 0; rr < 8; rr++) {
#pragma unroll
        for (int oo = 0; oo < 4; oo++) z[rr][oo] += bb[oo];
        float4 q = make_float4(z[rr][0], z[rr][1], z[rr][2], z[rr][3]);
        *(float4*)(g_m1 + base + (size_t)(r0 + rr) * 64 + og * 4) = q;   // z1 -> g_m1
    }
    emit_partials(z, redS, redQ, og, t, blockIdx.x);
}

// ================= reduce chain =================
__global__ void __launch_bounds__(128) reduce_stage1()
{
    const int c = threadIdx.x;
    const int b = blockIdx.x;
    float s = 0.f;
    for (int i = 0; i < 32; i++) s += g_part[((size_t)(b * 32 + i)) * 128 + c];
    g_red[(size_t)b * 128 + c] = s;
}
__global__ void __launch_bounds__(64) finalize_kernel(const float* __restrict__ g,
                                                      const float* __restrict__ be,
                                                      float* __restrict__ ss)
{
    const int c = threadIdx.x;
    double s = 0.0, q = 0.0;
    for (int r = 0; r < 256; r++) {
        s += (double)g_red[(size_t)r * 128 + c];
        q += (double)g_red[(size_t)r * 128 + 64 + c];
    }
    double mu  = s / (double)NROWS;
    double var = q / (double)NROWS - mu * mu;
    float sc = g[c] * rsqrtf((float)var + 1e-5f);
    ss[c]      = sc;
    ss[64 + c] = be[c] - (float)mu * sc;
}

// ================= K5: h1=BN1relu(z1); z2 = h1 @ uW2 + ub2, + partial stats =================
// smem: as 8192 | Wt 4096 | redS 1024 | redQ 1024 | ss 128
__global__ void __launch_bounds__(256, 1) gemm2_kernel(const float* __restrict__ uW2,
                                                       const float* __restrict__ ub2)
{
    extern __shared__ float sm[];
    float* as   = sm;
    float* Wt   = sm + 8192;
    float* redS = sm + 12288;
    float* redQ = sm + 13312;
    float* ss   = sm + 14336;
    const int t = threadIdx.x;
    const int og = t & 15;
    const int r0 = (t >> 4) * 8;
    const size_t base = (size_t)blockIdx.x * 8192;

    if (t < 128) ss[t] = g_ss1[t];
    stage_w_kmajor(uW2, Wt, 32, t, 256);
    __syncthreads();
    for (int i = t; i < 8192; i += 256) {
        int c = i & 63;
        float v = g_m1[base + i];                       // z1
        as[i] = fmaxf(v * ss[c] + ss[64 + c], 0.f);
    }
    __syncthreads();

    float z[8][4];
    gemm_tile<32, 64>(as, Wt, og, r0, z);
    float bb[4];
#pragma unroll
    for (int oo = 0; oo < 4; oo++) bb[oo] = __ldg(ub2 + og * 4 + oo);
#pragma unroll
    for (int rr = 0; rr < 8; rr++) {
#pragma unroll
        for (int oo = 0; oo < 4; oo++) z[rr][oo] += bb[oo];
        float4 q = make_float4(z[rr][0], z[rr][1], z[rr][2], z[rr][3]);
        *(float4*)(g_m2 + base + (size_t)(r0 + rr) * 64 + og * 4) = q;   // z2 -> g_m2
    }
    emit_partials(z, redS, redQ, og, t, blockIdx.x);
}

// ================= K7: out = BN2relu(z2) + x =================
__global__ void __launch_bounds__(256) final_kernel(const float* __restrict__ x,
                                                    float* __restrict__ out)
{
    __shared__ float ss[128];
    if (threadIdx.x < 128) ss[threadIdx.x] = g_ss2[threadIdx.x];
    __syncthreads();
    const size_t total4 = NROWS * 64 / 4;
    for (size_t v = (size_t)blockIdx.x * 256 + threadIdx.x; v < total4;
         v += (size_t)gridDim.x * 256) {
        int c0 = ((int)(v & 15)) * 4;
        float4 z = *(const float4*)((const float*)g_m2 + v * 4);
        float4 xv = *(const float4*)(x + v * 4);
        float4 o;
        o.x = fmaxf(z.x * ss[c0 + 0] + ss[64 + c0 + 0], 0.f) + xv.x;
        o.y = fmaxf(z.y * ss[c0 + 1] + ss[64 + c0 + 1], 0.f) + xv.y;
        o.z = fmaxf(z.z * ss[c0 + 2] + ss[64 + c0 + 2], 0.f) + xv.z;
        o.w = fmaxf(z.w * ss[c0 + 3] + ss[64 + c0 + 3], 0.f) + xv.w;
        *(float4*)(out + v * 4) = o;
    }
}

// ================= host =================
extern "C" void kernel_launch(void* const* d_in, const int* in_sizes, int n_in,
                              void* d_out, int out_size)
{
    const float* x    = (const float*)d_in[0];
    const float* w11  = (const float*)d_in[1];
    const float* b11  = (const float*)d_in[2];
    const float* w12  = (const float*)d_in[3];
    const float* b12  = (const float*)d_in[4];
    const float* w21  = (const float*)d_in[5];
    const float* b21  = (const float*)d_in[6];
    const float* w22  = (const float*)d_in[7];
    const float* b22  = (const float*)d_in[8];
    const float* uW1  = (const float*)d_in[9];
    const float* ub1  = (const float*)d_in[10];
    const float* g1   = (const float*)d_in[11];
    const float* be1  = (const float*)d_in[12];
    const float* uW2  = (const float*)d_in[13];
    const float* ub2  = (const float*)d_in[14];
    const float* g2   = (const float*)d_in[15];
    const float* be2  = (const float*)d_in[16];
    float* out = (float*)d_out;

    float *ss1, *ss2;
    cudaGetSymbolAddress((void**)&ss1, g_ss1);
    cudaGetSymbolAddress((void**)&ss2, g_ss2);

    cudaFuncSetAttribute(mlp_kernel,   cudaFuncAttributeMaxDynamicSharedMemorySize, 98304);
    cudaFuncSetAttribute(corr_kernel,  cudaFuncAttributeMaxDynamicSharedMemorySize, 73728);
    cudaFuncSetAttribute(gemm1_kernel, cudaFuncAttributeMaxDynamicSharedMemorySize, 106496);
    cudaFuncSetAttribute(gemm2_kernel, cudaFuncAttributeMaxDynamicSharedMemorySize, 58368);

    mlp_kernel<<<8192, 256, 98304>>>(x, w11, b11, w12, b12, w21, b21, w22, b22);
    corr_kernel<<<2048, 512, 73728>>>();
    gemm1_kernel<<<8192, 256, 106496>>>(x, uW1, ub1);
    reduce_stage1<<<256, 128>>>();
    finalize_kernel<<<1, 64>>>(g1, be1, ss1);
    gemm2_kernel<<<8192, 256, 58368>>>(uW2, ub2);
    reduce_stage1<<<256, 128>>>();
    finalize_kernel<<<1, 64>>>(g2, be2, ss2);
    final_kernel<<<16384, 256>>>(x, out);
}

// round 4
// speedup vs baseline: 1.0532x; 1.0532x over previous
#include <cuda_runtime.h>
#include <cuda_bf16.h>
#include <math.h>
#include <stdint.h>

typedef unsigned long long u64;
#define NROWS 1048576ull

// ==================== device globals (no runtime alloc) ====================
__device__ float g_m1[NROWS * 64];      // m1, reused as z1
__device__ float g_m2[NROWS * 64];      // m2, reused as z2
__device__ float g_h [NROWS * 64];      // sqrt(relu(corr))
__device__ float g_part[8192 * 128];    // per-CTA [sum(64)|sumsq(64)]
__device__ float g_red [256 * 128];
__device__ float g_ss1[128];            // BN1 [scale|shift]
__device__ float g_ss2[128];            // BN2
// 7 weight matrices as pre-swizzled SW128 images: [m][hi 8KB][lo 8KB]
// m: 0=w11 1=w12 2=w21 3=w22 ([n][k])  4=uW1^T k<64  5=uW1^T k>=64  6=uW2^T
__device__ __align__(16) unsigned char g_wimg[7 * 16384];

// ==================== helpers ====================
__device__ __forceinline__ uint32_t smem_u32(const void* p) {
    uint32_t a;
    asm("{ .reg .u64 t; cvta.to.shared.u64 t, %1; cvt.u32.u64 %0, t; }" : "=r"(a) : "l"(p));
    return a;
}
__device__ __forceinline__ uint32_t sw128(uint32_t b) { return b ^ ((b >> 3) & 0x70); }

__device__ __forceinline__ u64 ffma2(u64 acc, u64 a, u64 b) {
    u64 d;
    asm("fma.rn.f32x2 %0, %1, %2, %3;" : "=l"(d) : "l"(a), "l"(b), "l"(acc));
    return d;
}
__device__ __forceinline__ float2 u2f(u64 v) {
    float2 f;
    asm("mov.b64 {%0, %1}, %2;" : "=f"(f.x), "=f"(f.y) : "l"(v));
    return f;
}

__device__ __forceinline__ void split2(float2 v, uint32_t& hi, uint32_t& lo) {
    __nv_bfloat162 h2 = __float22bfloat162_rn(v);
    float2 hf = __bfloat1622float2(h2);
    __nv_bfloat162 l2 = __float22bfloat162_rn(make_float2(v.x - hf.x, v.y - hf.y));
    hi = *(uint32_t*)&h2;
    lo = *(uint32_t*)&l2;
}
// split fp32 pair -> bf16 hi/lo, store swizzled into 128B-row image
__device__ __forceinline__ void split_store(char* smp, uint32_t hiOff, uint32_t loOff,
                                            int row, int cp, float2 v) {
    uint32_t hi, lo;
    split2(v, hi, lo);
    uint32_t sw = sw128((uint32_t)(row * 128 + cp * 4));
    *(uint32_t*)(smp + hiOff + sw) = hi;
    *(uint32_t*)(smp + loOff + sw) = lo;
}

// ==================== HMMA building blocks (sm_80+; legal on plain sm_103) ====================
__device__ __forceinline__ void ldsm4(uint32_t addr, uint32_t r[4]) {
    asm volatile("ldmatrix.sync.aligned.m8n8.x4.shared.b16 {%0,%1,%2,%3}, [%4];"
        : "=r"(r[0]), "=r"(r[1]), "=r"(r[2]), "=r"(r[3]) : "r"(addr));
}
__device__ __forceinline__ void mma16816(float (&d)[4], const uint32_t (&a)[4],
                                         uint32_t b0, uint32_t b1) {
    asm volatile("mma.sync.aligned.m16n8k16.row.col.f32.bf16.bf16.f32 "
        "{%0,%1,%2,%3}, {%4,%5,%6,%7}, {%8,%9}, {%0,%1,%2,%3};"
        : "+f"(d[0]), "+f"(d[1]), "+f"(d[2]), "+f"(d[3])
        : "r"(a[0]), "r"(a[1]), "r"(a[2]), "r"(a[3]), "r"(b0), "r"(b1));
}

// warp computes D[16][64] (rows r0..r0+15) += A(16x64) * B(64x64)^T in 3 split passes.
// aH/aL, bH/bL: u32 smem base addresses of SW128 images (128B rows, 64 bf16/row).
__device__ __forceinline__ void warp_mma_k64(uint32_t aH, uint32_t aL,
                                             uint32_t bH, uint32_t bL,
                                             int r0, int lane, float (&acc)[8][4])
{
    const int grp = lane >> 3, li = lane & 7;
    const int arow = r0 + li + ((grp & 1) << 3);
    const uint32_t arbase = (uint32_t)(arow * 128);
    const uint32_t arxor = (uint32_t)((arow & 7) << 4);
    const int akhi = (grp >> 1) << 3;
    const int brow_off = li + ((grp >> 1) << 3);
    const int bkhi = (grp & 1) << 3;

#pragma unroll
    for (int pass = 0; pass < 3; pass++) {
        const uint32_t ab = (pass == 2) ? aL : aH;
        const uint32_t bb = (pass == 1) ? bL : bH;
#pragma unroll
        for (int kk = 0; kk < 4; kk++) {
            uint32_t a[4];
            uint32_t acb = (uint32_t)((kk * 16 + akhi) * 2);
            ldsm4(ab + arbase + (acb ^ arxor), a);
#pragma unroll
            for (int nt2 = 0; nt2 < 4; nt2++) {
                int brow = nt2 * 16 + brow_off;
                uint32_t bcb = (uint32_t)((kk * 16 + bkhi) * 2);
                uint32_t b[4];
                ldsm4(bb + (uint32_t)(brow * 128) + (bcb ^ (uint32_t)((brow & 7) << 4)), b);
                mma16816(acc[nt2 * 2],     a, b[0], b[1]);
                mma16816(acc[nt2 * 2 + 1], a, b[2], b[3]);
            }
        }
    }
}

// epilogue: relu(acc+bias) -> split-store into next-layer smem image (warp-private rows)
__device__ __forceinline__ void epi_to_img(float (&acc)[8][4], const float* bias,
                                           char* smp, uint32_t hiOff, uint32_t loOff,
                                           int r0, int lane)
{
    const int tr = lane >> 2, tc2 = lane & 3;
    const int r1 = r0 + tr, r2 = r1 + 8;
    const uint32_t x1 = (uint32_t)((r1 & 7) << 4), x2 = (uint32_t)((r2 & 7) << 4);
#pragma unroll
    for (int nt = 0; nt < 8; nt++) {
        int c0 = nt * 8 + 2 * tc2;
        float b0 = bias[c0], b1 = bias[c0 + 1];
        uint32_t cb = (uint32_t)(c0 * 2);
        uint32_t hi, lo;
        float2 v;
        v.x = fmaxf(acc[nt][0] + b0, 0.f);
        v.y = fmaxf(acc[nt][1] + b1, 0.f);
        split2(v, hi, lo);
        *(uint32_t*)(smp + hiOff + r1 * 128 + (cb ^ x1)) = hi;
        *(uint32_t*)(smp + loOff + r1 * 128 + (cb ^ x1)) = lo;
        v.x = fmaxf(acc[nt][2] + b0, 0.f);
        v.y = fmaxf(acc[nt][3] + b1, 0.f);
        split2(v, hi, lo);
        *(uint32_t*)(smp + hiOff + r2 * 128 + (cb ^ x2)) = hi;
        *(uint32_t*)(smp + loOff + r2 * 128 + (cb ^ x2)) = lo;
    }
}

// epilogue: acc+bias (optional relu) -> fp32 global rows (64 floats/row)
__device__ __forceinline__ void epi_to_global(float (&acc)[8][4], const float* bias,
                                              float* gdst, int r0, int lane, bool do_relu)
{
    const int tr = lane >> 2, tc2 = lane & 3;
    const int r1 = r0 + tr, r2 = r1 + 8;
#pragma unroll
    for (int nt = 0; nt < 8; nt++) {
        int c0 = nt * 8 + 2 * tc2;
        float b0 = bias[c0], b1 = bias[c0 + 1];
        float2 v0 = make_float2(acc[nt][0] + b0, acc[nt][1] + b1);
        float2 v1 = make_float2(acc[nt][2] + b0, acc[nt][3] + b1);
        if (do_relu) {
            v0.x = fmaxf(v0.x, 0.f); v0.y = fmaxf(v0.y, 0.f);
            v1.x = fmaxf(v1.x, 0.f); v1.y = fmaxf(v1.y, 0.f);
        }
        *(float2*)(gdst + (size_t)r1 * 64 + c0) = v0;
        *(float2*)(gdst + (size_t)r2 * 64 + c0) = v1;
    }
}

// ==================== prep: weights -> bf16 hi/lo SW128 images ====================
__global__ void prep_kernel(const float* __restrict__ w11, const float* __restrict__ w12,
                            const float* __restrict__ w21, const float* __restrict__ w22,
                            const float* __restrict__ uW1, const float* __restrict__ uW2)
{
    for (int idx = threadIdx.x; idx < 7 * 4096; idx += blockDim.x) {
        int m = idx >> 12, e = idx & 4095, n = e >> 6, k = e & 63;
        float v;
        if      (m == 0) v = w11[e];
        else if (m == 1) v = w12[e];
        else if (m == 2) v = w21[e];
        else if (m == 3) v = w22[e];
        else if (m == 4) v = uW1[k * 64 + n];
        else if (m == 5) v = uW1[(64 + k) * 64 + n];
        else             v = uW2[k * 64 + n];
        __nv_bfloat16 hi = __float2bfloat16(v);
        __nv_bfloat16 lo = __float2bfloat16(v - __bfloat162float(hi));
        uint32_t sw = sw128((uint32_t)(n * 128 + k * 2));
        *(__nv_bfloat16*)(g_wimg + m * 16384 + sw)        = hi;
        *(__nv_bfloat16*)(g_wimg + m * 16384 + 8192 + sw) = lo;
    }
}

// ==================== K1: fused 4-layer MLP pair (HMMA) ====================
#define MLP_XH 0u
#define MLP_XL 16384u
#define MLP_HH 32768u
#define MLP_HL 49152u
#define MLP_W  65536u       /* 4 x 16KB images */
#define MLP_BIAS 131072u    /* 256 floats */
#define MLP_SMEM 132096

__global__ void __launch_bounds__(256, 1) mlp_mma_kernel(const float* __restrict__ x,
    const float* __restrict__ b11, const float* __restrict__ b12,
    const float* __restrict__ b21, const float* __restrict__ b22)
{
    extern __shared__ __align__(16) char smp[];
    const uint32_t sb = smem_u32(smp);
    const int t = threadIdx.x;
    const int w = t >> 5, lane = t & 31;
    const int r0 = w * 16;
    const size_t base = (size_t)blockIdx.x * 8192;

    // stage 4 weight images (64KB) + biases
    {
        const uint4* src = (const uint4*)g_wimg;
        uint4* dst = (uint4*)(smp + MLP_W);
        for (int i = t; i < 4096; i += 256) dst[i] = src[i];
    }
    float* sbias = (float*)(smp + MLP_BIAS);
    if (t < 64) {
        sbias[t]       = b11[t];
        sbias[64 + t]  = b12[t];
        sbias[128 + t] = b21[t];
        sbias[192 + t] = b22[t];
    }
    // stage x split hi/lo swizzled
    for (int j = t; j < 4096; j += 256) {
        int row = j >> 5, cp = j & 31;
        float2 v = *(const float2*)(x + base + row * 64 + 2 * cp);
        split_store(smp, MLP_XH, MLP_XL, row, cp, v);
    }
    __syncthreads();

    float acc[8][4];

    // ---- MLP1 layer1: x -> h ----
#pragma unroll
    for (int i = 0; i < 8; i++) { acc[i][0]=acc[i][1]=acc[i][2]=acc[i][3]=0.f; }
    warp_mma_k64(sb + MLP_XH, sb + MLP_XL, sb + MLP_W + 0 * 16384, sb + MLP_W + 0 * 16384 + 8192, r0, lane, acc);
    epi_to_img(acc, sbias + 0, smp, MLP_HH, MLP_HL, r0, lane);
    __syncwarp();
    // ---- MLP1 layer2: h -> g_m1 ----
#pragma unroll
    for (int i = 0; i < 8; i++) { acc[i][0]=acc[i][1]=acc[i][2]=acc[i][3]=0.f; }
    warp_mma_k64(sb + MLP_HH, sb + MLP_HL, sb + MLP_W + 1 * 16384, sb + MLP_W + 1 * 16384 + 8192, r0, lane, acc);
    epi_to_global(acc, sbias + 64, g_m1 + base, r0, lane, true);
    __syncwarp();
    // ---- MLP2 layer1: x -> h ----
#pragma unroll
    for (int i = 0; i < 8; i++) { acc[i][0]=acc[i][1]=acc[i][2]=acc[i][3]=0.f; }
    warp_mma_k64(sb + MLP_XH, sb + MLP_XL, sb + MLP_W + 2 * 16384, sb + MLP_W + 2 * 16384 + 8192, r0, lane, acc);
    epi_to_img(acc, sbias + 128, smp, MLP_HH, MLP_HL, r0, lane);
    __syncwarp();
    // ---- MLP2 layer2: h -> g_m2 ----
#pragma unroll
    for (int i = 0; i < 8; i++) { acc[i][0]=acc[i][1]=acc[i][2]=acc[i][3]=0.f; }
    warp_mma_k64(sb + MLP_HH, sb + MLP_HL, sb + MLP_W + 3 * 16384, sb + MLP_W + 3 * 16384 + 8192, r0, lane, acc);
    epi_to_global(acc, sbias + 192, g_m2 + base, r0, lane, true);
}

// ==================== K2: corr + sqrt(relu)  (FFMA2 SIMT, proven) ====================
__global__ void __launch_bounds__(512, 1) corr_kernel()
{
    extern __shared__ float sm[];
    float* m1s = sm;          // [8i][4k][64c]  = 2048
    float* m2s = sm + 2048;   // [4k][64j][64c] = 16384
    const int t  = threadIdx.x;
    const int b  = blockIdx.x >> 3;
    const int i0 = (blockIdx.x & 7) * 8;
    const int cp = t & 31;
    const int jg = t >> 5;
    const float* M1 = g_m1 + (size_t)b * 262144 + (size_t)i0 * 4096;
    const float* M2 = g_m2 + (size_t)b * 262144;

    u64 acc[8][4];
#pragma unroll
    for (int ii = 0; ii < 8; ii++)
#pragma unroll
        for (int jj = 0; jj < 4; jj++) acc[ii][jj] = 0ull;

    for (int k0 = 0; k0 < 64; k0 += 4) {
        if (k0) __syncthreads();
        for (int i = t; i < 2048; i += 512) {
            int ii = i >> 8, kk = (i >> 6) & 3, c = i & 63;
            m1s[i] = M1[(size_t)ii * 4096 + (size_t)(k0 + kk) * 64 + c];
        }
        for (int i = t; i < 16384; i += 512) {
            int kk = i >> 12, rest = i & 4095;
            m2s[i] = M2[(size_t)(k0 + kk) * 4096 + rest];
        }
        __syncthreads();
#pragma unroll
        for (int kk = 0; kk < 4; kk++) {
            u64 a1[8];
#pragma unroll
            for (int ii = 0; ii < 8; ii++)
                a1[ii] = *(const u64*)(m1s + ii * 256 + kk * 64 + 2 * cp);
#pragma unroll
            for (int jj = 0; jj < 4; jj++) {
                u64 v = *(const u64*)(m2s + kk * 4096 + (jg * 4 + jj) * 64 + 2 * cp);
#pragma unroll
                for (int ii = 0; ii < 8; ii++) acc[ii][jj] = ffma2(acc[ii][jj], a1[ii], v);
            }
        }
    }
    float* H = g_h + (size_t)b * 262144 + (size_t)i0 * 4096;
#pragma unroll
    for (int ii = 0; ii < 8; ii++)
#pragma unroll
        for (int jj = 0; jj < 4; jj++) {
            float2 p = u2f(acc[ii][jj]);
            float2 o;
            o.x = sqrtf(fmaxf(p.x, 0.f));
            o.y = sqrtf(fmaxf(p.y, 0.f));
            *(float2*)(H + (size_t)(ii * 64 + jg * 4 + jj) * 64 + 2 * cp) = o;
        }
}

// ==================== K3: z1 = [x,h] @ uW1 + ub1 (HMMA) + stats ====================
#define G1_XH 0u
#define G1_XL 16384u
#define G1_HH 32768u
#define G1_HL 49152u
#define G1_W  65536u        /* m4,m5 images: 32KB */
#define G1_BIAS 98304u
#define G1_SPAD 98560u      /* 128*65 floats = 33280B */
#define G1_SMEM 131840

__global__ void __launch_bounds__(256, 1) gemm1_mma_kernel(const float* __restrict__ x,
                                                           const float* __restrict__ ub1)
{
    extern __shared__ __align__(16) char smp[];
    const uint32_t sb = smem_u32(smp);
    const int t = threadIdx.x;
    const int w = t >> 5, lane = t & 31;
    const int r0 = w * 16;
    const size_t base = (size_t)blockIdx.x * 8192;

    {
        const uint4* src = (const uint4*)(g_wimg + 4 * 16384);
        uint4* dst = (uint4*)(smp + G1_W);
        for (int i = t; i < 2048; i += 256) dst[i] = src[i];
    }
    float* sbias = (float*)(smp + G1_BIAS);
    if (t < 64) sbias[t] = ub1[t];
    for (int j = t; j < 4096; j += 256) {
        int row = j >> 5, cp = j & 31;
        float2 vx = *(const float2*)(x   + base + row * 64 + 2 * cp);
        float2 vh = *(const float2*)(g_h + base + row * 64 + 2 * cp);
        split_store(smp, G1_XH, G1_XL, row, cp, vx);
        split_store(smp, G1_HH, G1_HL, row, cp, vh);
    }
    __syncthreads();

    float acc[8][4];
#pragma unroll
    for (int i = 0; i < 8; i++) { acc[i][0]=acc[i][1]=acc[i][2]=acc[i][3]=0.f; }
    warp_mma_k64(sb + G1_XH, sb + G1_XL, sb + G1_W,         sb + G1_W + 8192,          r0, lane, acc);
    warp_mma_k64(sb + G1_HH, sb + G1_HL, sb + G1_W + 16384, sb + G1_W + 16384 + 8192,  r0, lane, acc);

    epi_to_global(acc, sbias, g_m1 + base, r0, lane, false);

    // stats via spad
    float* spad = (float*)(smp + G1_SPAD);
    const int tr = lane >> 2, tc2 = lane & 3;
    const int r1 = r0 + tr, r2 = r1 + 8;
#pragma unroll
    for (int nt = 0; nt < 8; nt++) {
        int c0 = nt * 8 + 2 * tc2;
        float b0 = sbias[c0], b1 = sbias[c0 + 1];
        spad[r1 * 65 + c0]     = acc[nt][0] + b0;
        spad[r1 * 65 + c0 + 1] = acc[nt][1] + b1;
        spad[r2 * 65 + c0]     = acc[nt][2] + b0;
        spad[r2 * 65 + c0 + 1] = acc[nt][3] + b1;
    }
    __syncthreads();
    if (t < 64) {
        float s = 0.f, q = 0.f;
        for (int rr = 0; rr < 128; rr++) { float v = spad[rr * 65 + t]; s += v; q += v * v; }
        g_part[(size_t)blockIdx.x * 128 + t]      = s;
        g_part[(size_t)blockIdx.x * 128 + 64 + t] = q;
    }
}

// ==================== reduce chain + finalize ====================
__global__ void __launch_bounds__(128) reduce_stage1()
{
    const int c = threadIdx.x;
    const int b = blockIdx.x;
    float s = 0.f;
    for (int i = 0; i < 32; i++) s += g_part[((size_t)(b * 32 + i)) * 128 + c];
    g_red[(size_t)b * 128 + c] = s;
}
__global__ void __launch_bounds__(64) finalize_kernel(const float* __restrict__ g,
                                                      const float* __restrict__ be,
                                                      float* __restrict__ ss)
{
    const int c = threadIdx.x;
    double s = 0.0, q = 0.0;
    for (int rr = 0; rr < 256; rr++) {
        s += (double)g_red[(size_t)rr * 128 + c];
        q += (double)g_red[(size_t)rr * 128 + 64 + c];
    }
    double mu  = s / (double)NROWS;
    double var = q / (double)NROWS - mu * mu;
    float sc = g[c] * rsqrtf((float)var + 1e-5f);
    ss[c]      = sc;
    ss[64 + c] = be[c] - (float)mu * sc;
}

// ==================== K5: z2 = BN1relu(z1) @ uW2 + ub2 (HMMA) + stats ====================
#define G2_AH 0u
#define G2_AL 16384u
#define G2_W  32768u        /* m6 image 16KB */
#define G2_BIAS 49152u
#define G2_SS   49408u
#define G2_SPAD 49920u
#define G2_SMEM 83200

__global__ void __launch_bounds__(256, 1) gemm2_mma_kernel(const float* __restrict__ ub2)
{
    extern __shared__ __align__(16) char smp[];
    const uint32_t sb = smem_u32(smp);
    const int t = threadIdx.x;
    const int w = t >> 5, lane = t & 31;
    const int r0 = w * 16;
    const size_t base = (size_t)blockIdx.x * 8192;

    {
        const uint4* src = (const uint4*)(g_wimg + 6 * 16384);
        uint4* dst = (uint4*)(smp + G2_W);
        for (int i = t; i < 1024; i += 256) dst[i] = src[i];
    }
    float* sbias = (float*)(smp + G2_BIAS);
    float* ss    = (float*)(smp + G2_SS);
    if (t < 64) sbias[t] = ub2[t];
    if (t < 128) ss[t] = g_ss1[t];
    __syncthreads();
    for (int j = t; j < 4096; j += 256) {
        int row = j >> 5, cp = j & 31;
        int c = 2 * cp;
        float2 v = *(const float2*)(g_m1 + base + row * 64 + c);
        float2 a;
        a.x = fmaxf(v.x * ss[c]     + ss[64 + c],     0.f);
        a.y = fmaxf(v.y * ss[c + 1] + ss[64 + c + 1], 0.f);
        split_store(smp, G2_AH, G2_AL, row, cp, a);
    }
    __syncthreads();

    float acc[8][4];
#pragma unroll
    for (int i = 0; i < 8; i++) { acc[i][0]=acc[i][1]=acc[i][2]=acc[i][3]=0.f; }
    warp_mma_k64(sb + G2_AH, sb + G2_AL, sb + G2_W, sb + G2_W + 8192, r0, lane, acc);

    epi_to_global(acc, sbias, g_m2 + base, r0, lane, false);

    float* spad = (float*)(smp + G2_SPAD);
    const int tr = lane >> 2, tc2 = lane & 3;
    const int r1 = r0 + tr, r2 = r1 + 8;
#pragma unroll
    for (int nt = 0; nt < 8; nt++) {
        int c0 = nt * 8 + 2 * tc2;
        float b0 = sbias[c0], b1 = sbias[c0 + 1];
        spad[r1 * 65 + c0]     = acc[nt][0] + b0;
        spad[r1 * 65 + c0 + 1] = acc[nt][1] + b1;
        spad[r2 * 65 + c0]     = acc[nt][2] + b0;
        spad[r2 * 65 + c0 + 1] = acc[nt][3] + b1;
    }
    __syncthreads();
    if (t < 64) {
        float s = 0.f, q = 0.f;
        for (int rr = 0; rr < 128; rr++) { float v = spad[rr * 65 + t]; s += v; q += v * v; }
        g_part[(size_t)blockIdx.x * 128 + t]      = s;
        g_part[(size_t)blockIdx.x * 128 + 64 + t] = q;
    }
}

// ==================== K7: out = BN2relu(z2) + x ====================
__global__ void __launch_bounds__(256) final_kernel(const float* __restrict__ x,
                                                    float* __restrict__ out)
{
    __shared__ float ss[128];
    if (threadIdx.x < 128) ss[threadIdx.x] = g_ss2[threadIdx.x];
    __syncthreads();
    const size_t total4 = NROWS * 64 / 4;
    for (size_t v = (size_t)blockIdx.x * 256 + threadIdx.x; v < total4;
         v += (size_t)gridDim.x * 256) {
        int c0 = ((int)(v & 15)) * 4;
        float4 z = *(const float4*)((const float*)g_m2 + v * 4);
        float4 xv = *(const float4*)(x + v * 4);
        float4 o;
        o.x = fmaxf(z.x * ss[c0 + 0] + ss[64 + c0 + 0], 0.f) + xv.x;
        o.y = fmaxf(z.y * ss[c0 + 1] + ss[64 + c0 + 1], 0.f) + xv.y;
        o.z = fmaxf(z.z * ss[c0 + 2] + ss[64 + c0 + 2], 0.f) + xv.z;
        o.w = fmaxf(z.w * ss[c0 + 3] + ss[64 + c0 + 3], 0.f) + xv.w;
        *(float4*)(out + v * 4) = o;
    }
}

// ==================== host ====================
extern "C" void kernel_launch(void* const* d_in, const int* in_sizes, int n_in,
                              void* d_out, int out_size)
{
    const float* x    = (const float*)d_in[0];
    const float* w11  = (const float*)d_in[1];
    const float* b11  = (const float*)d_in[2];
    const float* w12  = (const float*)d_in[3];
    const float* b12  = (const float*)d_in[4];
    const float* w21  = (const float*)d_in[5];
    const float* b21  = (const float*)d_in[6];
    const float* w22  = (const float*)d_in[7];
    const float* b22  = (const float*)d_in[8];
    const float* uW1  = (const float*)d_in[9];
    const float* ub1  = (const float*)d_in[10];
    const float* g1   = (const float*)d_in[11];
    const float* be1  = (const float*)d_in[12];
    const float* uW2  = (const float*)d_in[13];
    const float* ub2  = (const float*)d_in[14];
    const float* g2   = (const float*)d_in[15];
    const float* be2  = (const float*)d_in[16];
    float* out = (float*)d_out;

    float *ss1, *ss2;
    cudaGetSymbolAddress((void**)&ss1, g_ss1);
    cudaGetSymbolAddress((void**)&ss2, g_ss2);

    cudaFuncSetAttribute(mlp_mma_kernel,   cudaFuncAttributeMaxDynamicSharedMemorySize, MLP_SMEM);
    cudaFuncSetAttribute(corr_kernel,      cudaFuncAttributeMaxDynamicSharedMemorySize, 73728);
    cudaFuncSetAttribute(gemm1_mma_kernel, cudaFuncAttributeMaxDynamicSharedMemorySize, G1_SMEM);
    cudaFuncSetAttribute(gemm2_mma_kernel, cudaFuncAttributeMaxDynamicSharedMemorySize, G2_SMEM);

    prep_kernel<<<1, 256>>>(w11, w12, w21, w22, uW1, uW2);
    mlp_mma_kernel<<<8192, 256, MLP_SMEM>>>(x, b11, b12, b21, b22);
    corr_kernel<<<2048, 512, 73728>>>();
    gemm1_mma_kernel<<<8192, 256, G1_SMEM>>>(x, ub1);
    reduce_stage1<<<256, 128>>>();
    finalize_kernel<<<1, 64>>>(g1, be1, ss1);
    gemm2_mma_kernel<<<8192, 256, G2_SMEM>>>(ub2);
    reduce_stage1<<<256, 128>>>();
    finalize_kernel<<<1, 64>>>(g2, be2, ss2);
    final_kernel<<<16384, 256>>>(x, out);
}

// round 5
// speedup vs baseline: 1.7050x; 1.6190x over previous
#include <cuda_runtime.h>
#include <cuda_bf16.h>
#include <math.h>
#include <stdint.h>

typedef unsigned long long u64;
#define NROWS 1048576ull
#define NTILES 8192
#define NG 296            /* persistent grid: 2 CTAs x 148 SMs */

// ==================== device globals (no runtime alloc) ====================
__device__ float g_m1[NROWS * 64];      // m1, reused as z1
__device__ float g_m2[NROWS * 64];      // m2, reused as z2
__device__ float g_h [NROWS * 64];      // sqrt(relu(corr))
__device__ float g_part[NG * 128];      // per-CTA [sum(64)|sumsq(64)]
__device__ float g_ss1[128];            // BN1 [scale|shift]
__device__ float g_ss2[128];            // BN2
// 7 weight matrices as pre-swizzled SW128 images: [m][hi 8KB][lo 8KB]
// m: 0=w11 1=w12 2=w21 3=w22 ([n][k])  4=uW1^T k<64  5=uW1^T k>=64  6=uW2^T
__device__ __align__(16) unsigned char g_wimg[7 * 16384];

// ==================== helpers ====================
__device__ __forceinline__ uint32_t smem_u32(const void* p) {
    uint32_t a;
    asm("{ .reg .u64 t; cvta.to.shared.u64 t, %1; cvt.u32.u64 %0, t; }" : "=r"(a) : "l"(p));
    return a;
}
__device__ __forceinline__ uint32_t sw128(uint32_t b) { return b ^ ((b >> 3) & 0x70); }

__device__ __forceinline__ u64 ffma2(u64 acc, u64 a, u64 b) {
    u64 d;
    asm("fma.rn.f32x2 %0, %1, %2, %3;" : "=l"(d) : "l"(a), "l"(b), "l"(acc));
    return d;
}
__device__ __forceinline__ float2 u2f(u64 v) {
    float2 f;
    asm("mov.b64 {%0, %1}, %2;" : "=f"(f.x), "=f"(f.y) : "l"(v));
    return f;
}

__device__ __forceinline__ void split2(float2 v, uint32_t& hi, uint32_t& lo) {
    __nv_bfloat162 h2 = __float22bfloat162_rn(v);
    float2 hf = __bfloat1622float2(h2);
    __nv_bfloat162 l2 = __float22bfloat162_rn(make_float2(v.x - hf.x, v.y - hf.y));
    hi = *(uint32_t*)&h2;
    lo = *(uint32_t*)&l2;
}

// ==================== HMMA building blocks ====================
__device__ __forceinline__ void ldsm4(uint32_t addr, uint32_t r[4]) {
    asm volatile("ldmatrix.sync.aligned.m8n8.x4.shared.b16 {%0,%1,%2,%3}, [%4];"
        : "=r"(r[0]), "=r"(r[1]), "=r"(r[2]), "=r"(r[3]) : "r"(addr));
}
__device__ __forceinline__ void mma16816(float (&d)[4], const uint32_t (&a)[4],
                                         uint32_t b0, uint32_t b1) {
    asm volatile("mma.sync.aligned.m16n8k16.row.col.f32.bf16.bf16.f32 "
        "{%0,%1,%2,%3}, {%4,%5,%6,%7}, {%8,%9}, {%0,%1,%2,%3};"
        : "+f"(d[0]), "+f"(d[1]), "+f"(d[2]), "+f"(d[3])
        : "r"(a[0]), "r"(a[1]), "r"(a[2]), "r"(a[3]), "r"(b0), "r"(b1));
}

// Direct-register A fragment from a row-major [128][64] fp32 tile, split hi/lo.
__device__ __forceinline__ void load_a_direct(const float* __restrict__ tile, int r0,
                                              int kc, int lane,
                                              uint32_t ah[4], uint32_t al[4]) {
    const float* p = tile + (size_t)(r0 + (lane >> 2)) * 64 + kc * 16 + (lane & 3) * 2;
    float2 v00 = *(const float2*)p;
    float2 v01 = *(const float2*)(p + 8);
    float2 v10 = *(const float2*)(p + 512);
    float2 v11 = *(const float2*)(p + 520);
    split2(v00, ah[0], al[0]); split2(v10, ah[1], al[1]);
    split2(v01, ah[2], al[2]); split2(v11, ah[3], al[3]);
}

// Same but applies BN1-relu (scale/shift in smem ss[0..63]=scale, [64..127]=shift).
__device__ __forceinline__ void load_a_bn(const float* __restrict__ tile,
                                          const float* __restrict__ sss, int r0,
                                          int kc, int lane,
                                          uint32_t ah[4], uint32_t al[4]) {
    const int c = kc * 16 + (lane & 3) * 2;
    float2 s0 = *(const float2*)(sss + c),      s8 = *(const float2*)(sss + c + 8);
    float2 h0 = *(const float2*)(sss + 64 + c), h8 = *(const float2*)(sss + 64 + c + 8);
    const float* p = tile + (size_t)(r0 + (lane >> 2)) * 64 + c;
    float2 v00 = *(const float2*)p;
    float2 v01 = *(const float2*)(p + 8);
    float2 v10 = *(const float2*)(p + 512);
    float2 v11 = *(const float2*)(p + 520);
    v00.x = fmaxf(v00.x * s0.x + h0.x, 0.f); v00.y = fmaxf(v00.y * s0.y + h0.y, 0.f);
    v10.x = fmaxf(v10.x * s0.x + h0.x, 0.f); v10.y = fmaxf(v10.y * s0.y + h0.y, 0.f);
    v01.x = fmaxf(v01.x * s8.x + h8.x, 0.f); v01.y = fmaxf(v01.y * s8.y + h8.y, 0.f);
    v11.x = fmaxf(v11.x * s8.x + h8.x, 0.f); v11.y = fmaxf(v11.y * s8.y + h8.y, 0.f);
    split2(v00, ah[0], al[0]); split2(v10, ah[1], al[1]);
    split2(v01, ah[2], al[2]); split2(v11, ah[3], al[3]);
}

// One k16 step against B images (SW128), 3 split passes: Ah*Bh + Al*Bh + Ah*Bl.
__device__ __forceinline__ void mma_k16(uint32_t bH, uint32_t bL, int kc, int lane,
                                        const uint32_t (&ah)[4], const uint32_t (&al)[4],
                                        float (&acc)[8][4]) {
    const int grp = lane >> 3, li = lane & 7;
    const int brow_off = li + ((grp >> 1) << 3);
    const uint32_t cb = (uint32_t)((kc * 16 + ((grp & 1) << 3)) * 2);
#pragma unroll
    for (int n2 = 0; n2 < 4; n2++) {
        int brow = n2 * 16 + brow_off;
        uint32_t bx = (uint32_t)(brow * 128) + (cb ^ (uint32_t)((brow & 7) << 4));
        uint32_t bh[4], bl[4];
        ldsm4(bH + bx, bh);
        mma16816(acc[n2 * 2],     ah, bh[0], bh[1]);
        mma16816(acc[n2 * 2 + 1], ah, bh[2], bh[3]);
        mma16816(acc[n2 * 2],     al, bh[0], bh[1]);
        mma16816(acc[n2 * 2 + 1], al, bh[2], bh[3]);
        ldsm4(bL + bx, bl);
        mma16816(acc[n2 * 2],     ah, bl[0], bl[1]);
        mma16816(acc[n2 * 2 + 1], ah, bl[2], bl[3]);
    }
}

// Full K=64 matmul with A from an SW128 smem image (for MLP layer 2).
__device__ __forceinline__ void warp_mma_k64_img(uint32_t aH, uint32_t aL,
                                                 uint32_t bH, uint32_t bL,
                                                 int r0, int lane, float (&acc)[8][4])
{
    const int grp = lane >> 3, li = lane & 7;
    const int arow = r0 + li + ((grp & 1) << 3);
    const uint32_t arbase = (uint32_t)(arow * 128);
    const uint32_t arxor = (uint32_t)((arow & 7) << 4);
    const int akhi = (grp >> 1) << 3;
#pragma unroll
    for (int kk = 0; kk < 4; kk++) {
        uint32_t acb = (uint32_t)((kk * 16 + akhi) * 2);
        uint32_t ah[4], al[4];
        ldsm4(aH + arbase + (acb ^ arxor), ah);
        ldsm4(aL + arbase + (acb ^ arxor), al);
        mma_k16(bH, bL, kk, lane, ah, al, acc);
    }
}

// epilogue: relu(acc+bias) -> split-store into smem image (warp-private rows)
__device__ __forceinline__ void epi_to_img(float (&acc)[8][4], const float* bias,
                                           char* smp, uint32_t hiOff, uint32_t loOff,
                                           int r0, int lane)
{
    const int tr = lane >> 2, tc2 = lane & 3;
    const int r1 = r0 + tr, r2 = r1 + 8;
    const uint32_t x1 = (uint32_t)((r1 & 7) << 4), x2 = (uint32_t)((r2 & 7) << 4);
#pragma unroll
    for (int nt = 0; nt < 8; nt++) {
        int c0 = nt * 8 + 2 * tc2;
        float b0 = bias[c0], b1 = bias[c0 + 1];
        uint32_t cb = (uint32_t)(c0 * 2);
        uint32_t hi, lo;
        float2 v;
        v.x = fmaxf(acc[nt][0] + b0, 0.f);
        v.y = fmaxf(acc[nt][1] + b1, 0.f);
        split2(v, hi, lo);
        *(uint32_t*)(smp + hiOff + r1 * 128 + (cb ^ x1)) = hi;
        *(uint32_t*)(smp + loOff + r1 * 128 + (cb ^ x1)) = lo;
        v.x = fmaxf(acc[nt][2] + b0, 0.f);
        v.y = fmaxf(acc[nt][3] + b1, 0.f);
        split2(v, hi, lo);
        *(uint32_t*)(smp + hiOff + r2 * 128 + (cb ^ x2)) = hi;
        *(uint32_t*)(smp + loOff + r2 * 128 + (cb ^ x2)) = lo;
    }
}

// epilogue: relu(acc+bias) -> fp32 global rows
__device__ __forceinline__ void epi_to_global_relu(float (&acc)[8][4], const float* bias,
                                                   float* gdst, int r0, int lane)
{
    const int tr = lane >> 2, tc2 = lane & 3;
    const int r1 = r0 + tr, r2 = r1 + 8;
#pragma unroll
    for (int nt = 0; nt < 8; nt++) {
        int c0 = nt * 8 + 2 * tc2;
        float b0 = bias[c0], b1 = bias[c0 + 1];
        *(float2*)(gdst + (size_t)r1 * 64 + c0) =
            make_float2(fmaxf(acc[nt][0] + b0, 0.f), fmaxf(acc[nt][1] + b1, 0.f));
        *(float2*)(gdst + (size_t)r2 * 64 + c0) =
            make_float2(fmaxf(acc[nt][2] + b0, 0.f), fmaxf(acc[nt][3] + b1, 0.f));
    }
}

// epilogue: z=acc+bias -> global + warp shuffle-reduced sum/sumsq into red buffers
__device__ __forceinline__ void epi_stats(float (&acc)[8][4], const float* bias,
                                          float* gdst, int r0, int lane,
                                          float* red_s, float* red_q, int w)
{
    const int tr = lane >> 2, tc2 = lane & 3;
    const int r1 = r0 + tr, r2 = r1 + 8;
#pragma unroll
    for (int nt = 0; nt < 8; nt++) {
        int c0 = nt * 8 + 2 * tc2;
        float b0 = bias[c0], b1 = bias[c0 + 1];
        float z00 = acc[nt][0] + b0, z01 = acc[nt][1] + b1;
        float z10 = acc[nt][2] + b0, z11 = acc[nt][3] + b1;
        *(float2*)(gdst + (size_t)r1 * 64 + c0) = make_float2(z00, z01);
        *(float2*)(gdst + (size_t)r2 * 64 + c0) = make_float2(z10, z11);
        float s0 = z00 + z10, s1 = z01 + z11;
        float q0 = z00 * z00 + z10 * z10, q1 = z01 * z01 + z11 * z11;
#pragma unroll
        for (int m = 4; m < 32; m <<= 1) {
            s0 += __shfl_xor_sync(0xffffffffu, s0, m);
            s1 += __shfl_xor_sync(0xffffffffu, s1, m);
            q0 += __shfl_xor_sync(0xffffffffu, q0, m);
            q1 += __shfl_xor_sync(0xffffffffu, q1, m);
        }
        if (tr == 0) {
            red_s[w * 64 + c0]     = s0;
            red_s[w * 64 + c0 + 1] = s1;
            red_q[w * 64 + c0]     = q0;
            red_q[w * 64 + c0 + 1] = q1;
        }
    }
}

// ==================== prep: weights -> bf16 hi/lo SW128 images ====================
__global__ void prep_kernel(const float* __restrict__ w11, const float* __restrict__ w12,
                            const float* __restrict__ w21, const float* __restrict__ w22,
                            const float* __restrict__ uW1, const float* __restrict__ uW2)
{
    for (int idx = threadIdx.x; idx < 7 * 4096; idx += blockDim.x) {
        int m = idx >> 12, e = idx & 4095, n = e >> 6, k = e & 63;
        float v;
        if      (m == 0) v = w11[e];
        else if (m == 1) v = w12[e];
        else if (m == 2) v = w21[e];
        else if (m == 3) v = w22[e];
        else if (m == 4) v = uW1[k * 64 + n];
        else if (m == 5) v = uW1[(64 + k) * 64 + n];
        else             v = uW2[k * 64 + n];
        __nv_bfloat16 hi = __float2bfloat16(v);
        __nv_bfloat16 lo = __float2bfloat16(v - __bfloat162float(hi));
        uint32_t sw = sw128((uint32_t)(n * 128 + k * 2));
        *(__nv_bfloat16*)(g_wimg + m * 16384 + sw)        = hi;
        *(__nv_bfloat16*)(g_wimg + m * 16384 + 8192 + sw) = lo;
    }
}

// ==================== K1: fused 4-layer MLP pair, persistent multi-tile ====================
#define MLP_HH 0u
#define MLP_HL 16384u
#define MLP_W  32768u       /* 4 x 16KB images */
#define MLP_BIAS 98304u     /* 256 floats */
#define MLP_SMEM 99328

__global__ void __launch_bounds__(256, 2) mlp_mma_kernel(const float* __restrict__ x,
    const float* __restrict__ b11, const float* __restrict__ b12,
    const float* __restrict__ b21, const float* __restrict__ b22)
{
    extern __shared__ __align__(16) char smp[];
    const uint32_t sb = smem_u32(smp);
    const int t = threadIdx.x;
    const int w = t >> 5, lane = t & 31;
    const int r0 = w * 16;

    {
        const uint4* src = (const uint4*)g_wimg;
        uint4* dst = (uint4*)(smp + MLP_W);
        for (int i = t; i < 4096; i += 256) dst[i] = src[i];
    }
    float* sbias = (float*)(smp + MLP_BIAS);
    if (t < 64) {
        sbias[t]       = b11[t];
        sbias[64 + t]  = b12[t];
        sbias[128 + t] = b21[t];
        sbias[192 + t] = b22[t];
    }
    __syncthreads();

    for (int tile = blockIdx.x; tile < NTILES; tile += gridDim.x) {
        const size_t base = (size_t)tile * 8192;
        float acc[8][4];
        uint32_t ah[4], al[4];

        // MLP1 layer1: x (direct regs) -> h image
#pragma unroll
        for (int i = 0; i < 8; i++) { acc[i][0]=acc[i][1]=acc[i][2]=acc[i][3]=0.f; }
#pragma unroll
        for (int kc = 0; kc < 4; kc++) {
            load_a_direct(x + base, r0, kc, lane, ah, al);
            mma_k16(sb + MLP_W + 0 * 16384, sb + MLP_W + 0 * 16384 + 8192, kc, lane, ah, al, acc);
        }
        epi_to_img(acc, sbias + 0, smp, MLP_HH, MLP_HL, r0, lane);
        __syncwarp();
        // MLP1 layer2: h image -> g_m1
#pragma unroll
        for (int i = 0; i < 8; i++) { acc[i][0]=acc[i][1]=acc[i][2]=acc[i][3]=0.f; }
        warp_mma_k64_img(sb + MLP_HH, sb + MLP_HL,
                         sb + MLP_W + 1 * 16384, sb + MLP_W + 1 * 16384 + 8192, r0, lane, acc);
        epi_to_global_relu(acc, sbias + 64, g_m1 + base, r0, lane);
        __syncwarp();
        // MLP2 layer1: x -> h image (overwrite)
#pragma unroll
        for (int i = 0; i < 8; i++) { acc[i][0]=acc[i][1]=acc[i][2]=acc[i][3]=0.f; }
#pragma unroll
        for (int kc = 0; kc < 4; kc++) {
            load_a_direct(x + base, r0, kc, lane, ah, al);
            mma_k16(sb + MLP_W + 2 * 16384, sb + MLP_W + 2 * 16384 + 8192, kc, lane, ah, al, acc);
        }
        epi_to_img(acc, sbias + 128, smp, MLP_HH, MLP_HL, r0, lane);
        __syncwarp();
        // MLP2 layer2: h image -> g_m2
#pragma unroll
        for (int i = 0; i < 8; i++) { acc[i][0]=acc[i][1]=acc[i][2]=acc[i][3]=0.f; }
        warp_mma_k64_img(sb + MLP_HH, sb + MLP_HL,
                         sb + MLP_W + 3 * 16384, sb + MLP_W + 3 * 16384 + 8192, r0, lane, acc);
        epi_to_global_relu(acc, sbias + 192, g_m2 + base, r0, lane);
        __syncwarp();
    }
}

// ==================== K2: corr + sqrt(relu)  (FFMA2 SIMT, proven) ====================
__global__ void __launch_bounds__(512, 1) corr_kernel()
{
    extern __shared__ float sm[];
    float* m1s = sm;          // [8i][4k][64c]  = 2048
    float* m2s = sm + 2048;   // [4k][64j][64c] = 16384
    const int t  = threadIdx.x;
    const int b  = blockIdx.x >> 3;
    const int i0 = (blockIdx.x & 7) * 8;
    const int cp = t & 31;
    const int jg = t >> 5;
    const float* M1 = g_m1 + (size_t)b * 262144 + (size_t)i0 * 4096;
    const float* M2 = g_m2 + (size_t)b * 262144;

    u64 acc[8][4];
#pragma unroll
    for (int ii = 0; ii < 8; ii++)
#pragma unroll
        for (int jj = 0; jj < 4; jj++) acc[ii][jj] = 0ull;

    for (int k0 = 0; k0 < 64; k0 += 4) {
        if (k0) __syncthreads();
        for (int i = t; i < 2048; i += 512) {
            int ii = i >> 8, kk = (i >> 6) & 3, c = i & 63;
            m1s[i] = M1[(size_t)ii * 4096 + (size_t)(k0 + kk) * 64 + c];
        }
        for (int i = t; i < 16384; i += 512) {
            int kk = i >> 12, rest = i & 4095;
            m2s[i] = M2[(size_t)(k0 + kk) * 4096 + rest];
        }
        __syncthreads();
#pragma unroll
        for (int kk = 0; kk < 4; kk++) {
            u64 a1[8];
#pragma unroll
            for (int ii = 0; ii < 8; ii++)
                a1[ii] = *(const u64*)(m1s + ii * 256 + kk * 64 + 2 * cp);
#pragma unroll
            for (int jj = 0; jj < 4; jj++) {
                u64 v = *(const u64*)(m2s + kk * 4096 + (jg * 4 + jj) * 64 + 2 * cp);
#pragma unroll
                for (int ii = 0; ii < 8; ii++) acc[ii][jj] = ffma2(acc[ii][jj], a1[ii], v);
            }
        }
    }
    float* H = g_h + (size_t)b * 262144 + (size_t)i0 * 4096;
#pragma unroll
    for (int ii = 0; ii < 8; ii++)
#pragma unroll
        for (int jj = 0; jj < 4; jj++) {
            float2 p = u2f(acc[ii][jj]);
            float2 o;
            o.x = sqrtf(fmaxf(p.x, 0.f));
            o.y = sqrtf(fmaxf(p.y, 0.f));
            *(float2*)(H + (size_t)(ii * 64 + jg * 4 + jj) * 64 + 2 * cp) = o;
        }
}

// ==================== K3: z1 = [x,h] @ uW1 + ub1, persistent + stats ====================
#define G1_W    0u          /* m4 at 0, m5 at 16384 */
#define G1_REDS 32768u
#define G1_REDQ 34816u
#define G1_BIAS 36864u
#define G1_SMEM 37120

__global__ void __launch_bounds__(256, 2) gemm1_mma_kernel(const float* __restrict__ x,
                                                           const float* __restrict__ ub1)
{
    extern __shared__ __align__(16) char smp[];
    const uint32_t sb = smem_u32(smp);
    const int t = threadIdx.x;
    const int w = t >> 5, lane = t & 31;
    const int r0 = w * 16;
    float* red_s = (float*)(smp + G1_REDS);
    float* red_q = (float*)(smp + G1_REDQ);
    float* sbias = (float*)(smp + G1_BIAS);

    {
        const uint4* src = (const uint4*)(g_wimg + 4 * 16384);
        uint4* dst = (uint4*)smp;
        for (int i = t; i < 2048; i += 256) dst[i] = src[i];
    }
    if (t < 64) sbias[t] = ub1[t];
    __syncthreads();

    float s_run = 0.f, q_run = 0.f;

    for (int tile = blockIdx.x; tile < NTILES; tile += gridDim.x) {
        const size_t base = (size_t)tile * 8192;
        float acc[8][4];
        uint32_t ah[4], al[4];
#pragma unroll
        for (int i = 0; i < 8; i++) { acc[i][0]=acc[i][1]=acc[i][2]=acc[i][3]=0.f; }
#pragma unroll
        for (int kc = 0; kc < 4; kc++) {
            load_a_direct(x + base, r0, kc, lane, ah, al);
            mma_k16(sb + G1_W, sb + G1_W + 8192, kc, lane, ah, al, acc);
        }
#pragma unroll
        for (int kc = 0; kc < 4; kc++) {
            load_a_direct(g_h + base, r0, kc, lane, ah, al);
            mma_k16(sb + G1_W + 16384, sb + G1_W + 16384 + 8192, kc, lane, ah, al, acc);
        }
        epi_stats(acc, sbias, g_m1 + base, r0, lane, red_s, red_q, w);
        __syncthreads();
        if (t < 64) {
            float s = 0.f, q = 0.f;
#pragma unroll
            for (int ww = 0; ww < 8; ww++) { s += red_s[ww * 64 + t]; q += red_q[ww * 64 + t]; }
            s_run += s; q_run += q;
        }
        __syncthreads();
    }
    if (t < 64) {
        g_part[(size_t)blockIdx.x * 128 + t]      = s_run;
        g_part[(size_t)blockIdx.x * 128 + 64 + t] = q_run;
    }
}

// ==================== finalize: BN scale/shift from partials ====================
__global__ void __launch_bounds__(64) finalize_kernel(const float* __restrict__ g,
                                                      const float* __restrict__ be,
                                                      float* __restrict__ ss)
{
    const int c = threadIdx.x;
    double s = 0.0, q = 0.0;
    for (int i = 0; i < NG; i++) {
        s += (double)g_part[(size_t)i * 128 + c];
        q += (double)g_part[(size_t)i * 128 + 64 + c];
    }
    double mu  = s / (double)NROWS;
    double var = q / (double)NROWS - mu * mu;
    float sc = g[c] * rsqrtf((float)var + 1e-5f);
    ss[c]      = sc;
    ss[64 + c] = be[c] - (float)mu * sc;
}

// ==================== K5: z2 = BN1relu(z1) @ uW2 + ub2, persistent + stats ====================
#define G2_W    0u
#define G2_REDS 16384u
#define G2_REDQ 18432u
#define G2_BIAS 20480u
#define G2_SS   20736u
#define G2_SMEM 21248

__global__ void __launch_bounds__(256, 2) gemm2_mma_kernel(const float* __restrict__ ub2)
{
    extern __shared__ __align__(16) char smp[];
    const uint32_t sb = smem_u32(smp);
    const int t = threadIdx.x;
    const int w = t >> 5, lane = t & 31;
    const int r0 = w * 16;
    float* red_s = (float*)(smp + G2_REDS);
    float* red_q = (float*)(smp + G2_REDQ);
    float* sbias = (float*)(smp + G2_BIAS);
    float* ss    = (float*)(smp + G2_SS);

    {
        const uint4* src = (const uint4*)(g_wimg + 6 * 16384);
        uint4* dst = (uint4*)smp;
        for (int i = t; i < 1024; i += 256) dst[i] = src[i];
    }
    if (t < 64) sbias[t] = ub2[t];
    if (t < 128) ss[t] = g_ss1[t];
    __syncthreads();

    float s_run = 0.f, q_run = 0.f;

    for (int tile = blockIdx.x; tile < NTILES; tile += gridDim.x) {
        const size_t base = (size_t)tile * 8192;
        float acc[8][4];
        uint32_t ah[4], al[4];
#pragma unroll
        for (int i = 0; i < 8; i++) { acc[i][0]=acc[i][1]=acc[i][2]=acc[i][3]=0.f; }
#pragma unroll
        for (int kc = 0; kc < 4; kc++) {
            load_a_bn(g_m1 + base, ss, r0, kc, lane, ah, al);
            mma_k16(sb + G2_W, sb + G2_W + 8192, kc, lane, ah, al, acc);
        }
        epi_stats(acc, sbias, g_m2 + base, r0, lane, red_s, red_q, w);
        __syncthreads();
        if (t < 64) {
            float s = 0.f, q = 0.f;
#pragma unroll
            for (int ww = 0; ww < 8; ww++) { s += red_s[ww * 64 + t]; q += red_q[ww * 64 + t]; }
            s_run += s; q_run += q;
        }
        __syncthreads();
    }
    if (t < 64) {
        g_part[(size_t)blockIdx.x * 128 + t]      = s_run;
        g_part[(size_t)blockIdx.x * 128 + 64 + t] = q_run;
    }
}

// ==================== K7: out = BN2relu(z2) + x ====================
__global__ void __launch_bounds__(256) final_kernel(const float* __restrict__ x,
                                                    float* __restrict__ out)
{
    __shared__ float ss[128];
    if (threadIdx.x < 128) ss[threadIdx.x] = g_ss2[threadIdx.x];
    __syncthreads();
    const size_t total4 = NROWS * 64 / 4;
    for (size_t v = (size_t)blockIdx.x * 256 + threadIdx.x; v < total4;
         v += (size_t)gridDim.x * 256) {
        int c0 = ((int)(v & 15)) * 4;
        float4 z = *(const float4*)((const float*)g_m2 + v * 4);
        float4 xv = *(const float4*)(x + v * 4);
        float4 o;
        o.x = fmaxf(z.x * ss[c0 + 0] + ss[64 + c0 + 0], 0.f) + xv.x;
        o.y = fmaxf(z.y * ss[c0 + 1] + ss[64 + c0 + 1], 0.f) + xv.y;
        o.z = fmaxf(z.z * ss[c0 + 2] + ss[64 + c0 + 2], 0.f) + xv.z;
        o.w = fmaxf(z.w * ss[c0 + 3] + ss[64 + c0 + 3], 0.f) + xv.w;
        *(float4*)(out + v * 4) = o;
    }
}

// ==================== host ====================
extern "C" void kernel_launch(void* const* d_in, const int* in_sizes, int n_in,
                              void* d_out, int out_size)
{
    const float* x    = (const float*)d_in[0];
    const float* w11  = (const float*)d_in[1];
    const float* b11  = (const float*)d_in[2];
    const float* w12  = (const float*)d_in[3];
    const float* b12  = (const float*)d_in[4];
    const float* w21  = (const float*)d_in[5];
    const float* b21  = (const float*)d_in[6];
    const float* w22  = (const float*)d_in[7];
    const float* b22  = (const float*)d_in[8];
    const float* uW1  = (const float*)d_in[9];
    const float* ub1  = (const float*)d_in[10];
    const float* g1   = (const float*)d_in[11];
    const float* be1  = (const float*)d_in[12];
    const float* uW2  = (const float*)d_in[13];
    const float* ub2  = (const float*)d_in[14];
    const float* g2   = (const float*)d_in[15];
    const float* be2  = (const float*)d_in[16];
    float* out = (float*)d_out;

    float *ss1, *ss2;
    cudaGetSymbolAddress((void**)&ss1, g_ss1);
    cudaGetSymbolAddress((void**)&ss2, g_ss2);

    cudaFuncSetAttribute(mlp_mma_kernel,   cudaFuncAttributeMaxDynamicSharedMemorySize, MLP_SMEM);
    cudaFuncSetAttribute(corr_kernel,      cudaFuncAttributeMaxDynamicSharedMemorySize, 73728);
    cudaFuncSetAttribute(gemm1_mma_kernel, cudaFuncAttributeMaxDynamicSharedMemorySize, G1_SMEM);
    cudaFuncSetAttribute(gemm2_mma_kernel, cudaFuncAttributeMaxDynamicSharedMemorySize, G2_SMEM);

    prep_kernel<<<1, 256>>>(w11, w12, w21, w22, uW1, uW2);
    mlp_mma_kernel<<<NG, 256, MLP_SMEM>>>(x, b11, b12, b21, b22);
    corr_kernel<<<2048, 512, 73728>>>();
    gemm1_mma_kernel<<<NG, 256, G1_SMEM>>>(x, ub1);
    finalize_kernel<<<1, 64>>>(g1, be1, ss1);
    gemm2_mma_kernel<<<NG, 256, G2_SMEM>>>(ub2);
    finalize_kernel<<<1, 64>>>(g2, be2, ss2);
    final_kernel<<<16384, 256>>>(x, out);
}